// round 7
// baseline (speedup 1.0000x reference)
#include <cuda_runtime.h>

#define NT 512
#define L_IN 4096
#define DZV 30
#define CV 10
#define NPG 15
#define B_TOT 512

typedef unsigned long long u64;

__constant__ float cWh[DZV*80];   // [d][c][j]
__constant__ float cZ[DZV];

// per-net block of 408 u64, all weights pre-duplicated (w,w):
// [0..96)    conv1: [chq<4][ch2<2][k<3][oc<4]
// [96..192)  conv2: [octile<2][ch<4][k<3][o4<4]
// [192..384) conv3: [octile<2][chq<4][ch2<2][k<3][o4<4]
// [384..388) b1d[4], [388..396) b2d[8], [396..404) b3d[8], pad 408
__device__ u64 g_wdup[DZV*408];

__device__ __forceinline__ u64 pack2(float a, float b) {
    u64 r; asm("mov.b64 %0, {%1, %2};" : "=l"(r) : "f"(a), "f"(b)); return r;
}
__device__ __forceinline__ void unpack2(u64 v, float& lo, float& hi) {
    asm("mov.b64 {%0, %1}, %2;" : "=f"(lo), "=f"(hi) : "l"(v));
}
__device__ __forceinline__ u64 ffma2(u64 a, u64 b, u64 c) {
    u64 d; asm("fma.rn.f32x2 %0, %1, %2, %3;" : "=l"(d) : "l"(a), "l"(b), "l"(c)); return d;
}
// one tap: 4 oc accumulators, dup'd weights in (wa, wb)
__device__ __forceinline__ void tap4(u64* acc, u64 t, ulonglong2 wa, ulonglong2 wb) {
    acc[0] = ffma2(wa.x, t, acc[0]);
    acc[1] = ffma2(wa.y, t, acc[1]);
    acc[2] = ffma2(wb.x, t, acc[2]);
    acc[3] = ffma2(wb.y, t, acc[3]);
}

__global__ void prep_kernel(const float* __restrict__ W1, const float* __restrict__ b1,
                            const float* __restrict__ W2, const float* __restrict__ b2,
                            const float* __restrict__ W3, const float* __restrict__ b3,
                            const float* __restrict__ z,  const float* __restrict__ bh,
                            float* __restrict__ out) {
    int i = blockIdx.x * blockDim.x + threadIdx.x;
    if (i < DZV*404) {
        int n = i / 404, r = i % 404;
        float v;
        if (r < 96) {
            int chq = r / 24, t = r % 24;
            int ch2 = t / 12, k = (t % 12) / 4, oc = t & 3;
            int ch = chq*2 + ch2;
            v = W1[n*96 + oc*24 + ch*3 + k];
        } else if (r < 192) {
            int t = r - 96;
            int octile = t / 48, t2 = t % 48;
            int ch = t2 / 12, k = (t2 % 12) / 4, o4 = t2 & 3;
            v = W2[n*96 + (octile*4 + o4)*12 + ch*3 + k];
        } else if (r < 384) {
            int t = r - 192;
            int octile = t / 96, t2 = t % 96;
            int cq = t2 / 24, t3 = t2 % 24;
            int ch2 = t3 / 12, k = (t3 % 12) / 4, o4 = t3 & 3;
            int ch = cq*2 + ch2;
            v = W3[n*192 + (octile*4 + o4)*24 + ch*3 + k];
        } else if (r < 388) v = b1[n*4 + (r-384)];
        else if (r < 396)   v = b2[n*8 + (r-388)];
        else                v = b3[n*8 + (r-396)];
        g_wdup[n*408 + r] = pack2(v, v);
    }
    if (i < B_TOT*CV) {
        int c = i % CV;
        float s = 0.f;
        #pragma unroll
        for (int d = 0; d < DZV; d++) s = fmaf(z[d], bh[d*CV + c], s);
        out[i] = s;
    }
}

// ---- smem float offsets ----
#define XE_BASE 0           // [8][2056]
#define XO_BASE 16448       // [8][2056]
#define HE_BASE 32896       // [4][1032]
#define HO_BASE 37024       // [4][1032]
#define H2_BASE 41152       // [8][1032]
#define RED_OFF 49408       // [16 warps][4]
#define SMEM_FLOATS 49472   // 197888 B

__global__ __launch_bounds__(NT, 1)
void ensemble_kernel(const int* __restrict__ ids,
                     const float* __restrict__ mask,
                     const float* __restrict__ embed,
                     float* __restrict__ out)
{
    extern __shared__ float sm[];
    float* red = sm + RED_OFF;

    const int tid  = threadIdx.x;
    const int lane = tid & 31;
    const int warp = tid >> 5;
    const int b    = blockIdx.x;
    const int g    = blockIdx.y;
    const int octile = tid >> 8;        // 0/1 for conv2, conv3
    const int pb     = tid & 255;       // 0..255 for conv2, conv3

    // ---- zero pads (written once; never overwritten by conv stores) ----
    if (tid < 8)                sm[XE_BASE + tid*2056 + 2048] = 0.f;
    else if (tid < 12)          sm[HE_BASE + (tid-8)*1032 + 1024] = 0.f;
    else if (tid >= 16 && tid < 32)
        sm[H2_BASE + ((tid-16)>>1)*1032 + 1024 + (tid & 1)] = 0.f;

    // ---- gather masked embeddings, channel-major, even/odd deinterleaved ----
    #pragma unroll 1
    for (int i = tid; i < L_IN; i += NT) {
        int   id = __ldg(&ids[b*L_IN + i]);
        float m  = __ldg(&mask[b*L_IN + i]);
        float4 e0 = __ldg((const float4*)(embed + (size_t)id*8));
        float4 e1 = __ldg((const float4*)(embed + (size_t)id*8 + 4));
        int base = ((i & 1) ? XO_BASE : XE_BASE) + (i >> 1);
        sm[base + 0*2056] = e0.x*m; sm[base + 1*2056] = e0.y*m;
        sm[base + 2*2056] = e0.z*m; sm[base + 3*2056] = e0.w*m;
        sm[base + 4*2056] = e1.x*m; sm[base + 5*2056] = e1.y*m;
        sm[base + 6*2056] = e1.z*m; sm[base + 7*2056] = e1.w*m;
    }
    __syncthreads();

    float oacc = 0.f;   // warp0, lane<CV

    #pragma unroll 1
    for (int dn = 0; dn < NPG; dn++) {
        const int d = g*NPG + dn;
        const u64* WB = g_wdup + (size_t)d*408;

        // ======== conv1: K3 S2, 8->4ch, ReLU. thread: pos 4*tid..4*tid+3, all 4 oc ========
        {
            u64 acc[2][4];   // [pair j][oc]
            {
                ulonglong2 b0 = __ldg((const ulonglong2*)(WB + 384));
                ulonglong2 b1 = __ldg((const ulonglong2*)(WB + 386));
                acc[0][0]=b0.x; acc[0][1]=b0.y; acc[0][2]=b1.x; acc[0][3]=b1.y;
                acc[1][0]=b0.x; acc[1][1]=b0.y; acc[1][2]=b1.x; acc[1][3]=b1.y;
            }
            #pragma unroll
            for (int cq = 0; cq < 4; cq++) {
                ulonglong2 w[12];
                #pragma unroll
                for (int i = 0; i < 12; i++)
                    w[i] = __ldg((const ulonglong2*)(WB + cq*24) + i);
                #pragma unroll
                for (int c2 = 0; c2 < 2; c2++) {
                    const int ch = cq*2 + c2;
                    const float* XEr = sm + XE_BASE + ch*2056 + 4*tid;
                    const float* XOr = sm + XO_BASE + ch*2056 + 4*tid;
                    float4 A = *(const float4*)XEr;
                    float  e = XEr[4];
                    float4 C = *(const float4*)XOr;
                    const ulonglong2* wc = w + c2*6;   // [k<3][ocpair<2]
                    // pair 0: taps (A.x,A.y) (C.x,C.y) (A.y,A.z)
                    tap4(acc[0], pack2(A.x,A.y), wc[0], wc[1]);
                    tap4(acc[0], pack2(C.x,C.y), wc[2], wc[3]);
                    tap4(acc[0], pack2(A.y,A.z), wc[4], wc[5]);
                    // pair 1: taps (A.z,A.w) (C.z,C.w) (A.w,e)
                    tap4(acc[1], pack2(A.z,A.w), wc[0], wc[1]);
                    tap4(acc[1], pack2(C.z,C.w), wc[2], wc[3]);
                    tap4(acc[1], pack2(A.w,e),   wc[4], wc[5]);
                }
            }
            // stores: pos 4t..4t+3 -> HE[oc][2t..2t+1], HO[oc][2t..2t+1]
            #pragma unroll
            for (int oc = 0; oc < 4; oc++) {
                float l0,h0,l1,h1;
                unpack2(acc[0][oc], l0, h0);
                unpack2(acc[1][oc], l1, h1);
                *(float2*)(sm + HE_BASE + oc*1032 + 2*tid) =
                    make_float2(fmaxf(l0,0.f), fmaxf(l1,0.f));
                *(float2*)(sm + HO_BASE + oc*1032 + 2*tid) =
                    make_float2(fmaxf(h0,0.f), fmaxf(h1,0.f));
            }
        }
        __syncthreads();

        // ======== conv2: K3 S2, 4->8ch, ReLU. thread: pos 4*pb..4*pb+3, oc octile*4.. ========
        {
            u64 acc[2][4];
            {
                ulonglong2 b0 = __ldg((const ulonglong2*)(WB + 388 + octile*4));
                ulonglong2 b1 = __ldg((const ulonglong2*)(WB + 390 + octile*4));
                acc[0][0]=b0.x; acc[0][1]=b0.y; acc[0][2]=b1.x; acc[0][3]=b1.y;
                acc[1][0]=b0.x; acc[1][1]=b0.y; acc[1][2]=b1.x; acc[1][3]=b1.y;
            }
            #pragma unroll
            for (int chh = 0; chh < 2; chh++) {
                ulonglong2 w[12];
                #pragma unroll
                for (int i = 0; i < 12; i++)
                    w[i] = __ldg((const ulonglong2*)(WB + 96 + octile*48 + chh*24) + i);
                #pragma unroll
                for (int c2 = 0; c2 < 2; c2++) {
                    const int ch = chh*2 + c2;
                    const float* HEr = sm + HE_BASE + ch*1032 + 4*pb;
                    const float* HOr = sm + HO_BASE + ch*1032 + 4*pb;
                    float4 A = *(const float4*)HEr;
                    float  e = HEr[4];
                    float4 C = *(const float4*)HOr;
                    const ulonglong2* wc = w + c2*6;
                    tap4(acc[0], pack2(A.x,A.y), wc[0], wc[1]);
                    tap4(acc[0], pack2(C.x,C.y), wc[2], wc[3]);
                    tap4(acc[0], pack2(A.y,A.z), wc[4], wc[5]);
                    tap4(acc[1], pack2(A.z,A.w), wc[0], wc[1]);
                    tap4(acc[1], pack2(C.z,C.w), wc[2], wc[3]);
                    tap4(acc[1], pack2(A.w,e),   wc[4], wc[5]);
                }
            }
            // stores: h2[oc][4pb..4pb+3], oc = octile*4 + o
            #pragma unroll
            for (int o = 0; o < 4; o++) {
                float l0,h0,l1,h1;
                unpack2(acc[0][o], l0, h0);
                unpack2(acc[1][o], l1, h1);
                *(float4*)(sm + H2_BASE + (octile*4+o)*1032 + 4*pb) =
                    make_float4(fmaxf(l0,0.f), fmaxf(h0,0.f), fmaxf(l1,0.f), fmaxf(h1,0.f));
            }
        }
        __syncthreads();

        // ======== conv3: K3 S1, 8->8ch, ReLU+pool. thread: pos 4*pb..4*pb+3, oc octile*4.. ========
        float psum[4] = {0.f, 0.f, 0.f, 0.f};
        {
            u64 acc[2][4];
            {
                ulonglong2 b0 = __ldg((const ulonglong2*)(WB + 396 + octile*4));
                ulonglong2 b1 = __ldg((const ulonglong2*)(WB + 398 + octile*4));
                acc[0][0]=b0.x; acc[0][1]=b0.y; acc[0][2]=b1.x; acc[0][3]=b1.y;
                acc[1][0]=b0.x; acc[1][1]=b0.y; acc[1][2]=b1.x; acc[1][3]=b1.y;
            }
            #pragma unroll
            for (int cq = 0; cq < 4; cq++) {
                ulonglong2 w[12];
                #pragma unroll
                for (int i = 0; i < 12; i++)
                    w[i] = __ldg((const ulonglong2*)(WB + 192 + octile*96 + cq*24) + i);
                #pragma unroll
                for (int c2 = 0; c2 < 2; c2++) {
                    const int ch = cq*2 + c2;
                    const float* H2r = sm + H2_BASE + ch*1032 + 4*pb;
                    float4 A = *(const float4*)H2r;
                    float2 E = *(const float2*)(H2r + 4);
                    const ulonglong2* wc = w + c2*6;
                    // pair 0 (p, p+1): taps (A.x,A.y) (A.y,A.z) (A.z,A.w)
                    tap4(acc[0], pack2(A.x,A.y), wc[0], wc[1]);
                    tap4(acc[0], pack2(A.y,A.z), wc[2], wc[3]);
                    tap4(acc[0], pack2(A.z,A.w), wc[4], wc[5]);
                    // pair 1 (p+2, p+3): taps (A.z,A.w) (A.w,E.x) (E.x,E.y)
                    tap4(acc[1], pack2(A.z,A.w), wc[0], wc[1]);
                    tap4(acc[1], pack2(A.w,E.x), wc[2], wc[3]);
                    tap4(acc[1], pack2(E.x,E.y), wc[4], wc[5]);
                }
            }
            const int p = 4*pb;
            const bool v0 = (p     < 1021), v1 = (p + 1 < 1021);
            const bool v2 = (p + 2 < 1021), v3 = (p + 3 < 1021);
            #pragma unroll
            for (int o = 0; o < 4; o++) {
                float l0,h0,l1,h1;
                unpack2(acc[0][o], l0, h0);
                unpack2(acc[1][o], l1, h1);
                psum[o] += (v0 ? fmaxf(l0,0.f) : 0.f) + (v1 ? fmaxf(h0,0.f) : 0.f)
                         + (v2 ? fmaxf(l1,0.f) : 0.f) + (v3 ? fmaxf(h1,0.f) : 0.f);
            }
        }

        // ---- warp reduce psum[4] -> red[warp][4] ----
        #pragma unroll
        for (int o = 0; o < 4; o++) {
            float s = psum[o];
            #pragma unroll
            for (int off = 16; off > 0; off >>= 1)
                s += __shfl_down_sync(0xFFFFFFFFu, s, off);
            if (lane == 0) red[warp*4 + o] = s;
        }
        __syncthreads();

        // ---- warp0: cross-warp reduce + head matvec ----
        if (warp == 0) {
            float sa = red[lane];        // warps 0-7  (octile0): oc = lane&3
            float sb = red[lane + 32];   // warps 8-15 (octile1): oc = 4 + (lane&3)
            sa += __shfl_xor_sync(0xFFFFFFFFu, sa, 4);
            sa += __shfl_xor_sync(0xFFFFFFFFu, sa, 8);
            sa += __shfl_xor_sync(0xFFFFFFFFu, sa, 16);
            sb += __shfl_xor_sync(0xFFFFFFFFu, sb, 4);
            sb += __shfl_xor_sync(0xFFFFFFFFu, sb, 8);
            sb += __shfl_xor_sync(0xFFFFFFFFu, sb, 16);
            float pj[8];
            #pragma unroll
            for (int j = 0; j < 4; j++) {
                pj[j]   = __shfl_sync(0xFFFFFFFFu, sa, j);
                pj[4+j] = __shfl_sync(0xFFFFFFFFu, sb, j);
            }
            if (lane < CV) {
                float v = 0.f;
                #pragma unroll
                for (int j = 0; j < 8; j++)
                    v = fmaf(pj[j], cWh[(d*CV + lane)*8 + j], v);
                oacc = fmaf(v, cZ[d] * (1.0f/1021.0f), oacc);
            }
        }
        // red hazard: next red-write only after conv1+conv2 syncs of next net.
    }

    if (warp == 0 && lane < CV)
        atomicAdd(&out[b*CV + lane], oacc);
}

extern "C" void kernel_launch(void* const* d_in, const int* in_sizes, int n_in,
                              void* d_out, int out_size) {
    const int*   ids  = (const int*)  d_in[0];
    const float* mask = (const float*)d_in[1];
    const float* z    = (const float*)d_in[2];
    const float* emb  = (const float*)d_in[3];
    const float* W1   = (const float*)d_in[4];
    const float* b1   = (const float*)d_in[5];
    const float* W2   = (const float*)d_in[6];
    const float* b2   = (const float*)d_in[7];
    const float* W3   = (const float*)d_in[8];
    const float* b3   = (const float*)d_in[9];
    const float* Wh   = (const float*)d_in[10];
    const float* bh   = (const float*)d_in[11];
    float* out = (float*)d_out;

    cudaMemcpyToSymbolAsync(cWh, Wh, DZV*80*sizeof(float), 0, cudaMemcpyDeviceToDevice, 0);
    cudaMemcpyToSymbolAsync(cZ,  z,  DZV*sizeof(float),    0, cudaMemcpyDeviceToDevice, 0);

    prep_kernel<<<(DZV*404 + 255)/256, 256>>>(W1, b1, W2, b2, W3, b3, z, bh, out);

    cudaFuncSetAttribute(ensemble_kernel,
                         cudaFuncAttributeMaxDynamicSharedMemorySize,
                         SMEM_FLOATS * (int)sizeof(float));
    ensemble_kernel<<<dim3(B_TOT, 2), NT, SMEM_FLOATS * (int)sizeof(float)>>>(ids, mask, emb, out);
}